// round 8
// baseline (speedup 1.0000x reference)
#include <cuda_runtime.h>
#include <cuda_fp16.h>
#include <cstdint>

#define NF  16384   // n_features
#define ND  768     // d_model
#define NBS 1024    // B*S
#define NM  262144  // n_connections

// Scratch (device globals — no cudaMalloc allowed)
__device__ __align__(16) __half g_decH[(size_t)NF * ND];   // up_decoder transposed [F, D] fp16
__device__ __align__(16) __half g_upH [(size_t)NF * NBS];  // up_facts transposed  [F, BS] fp16
__device__ __align__(16) float  g_vals[NM];
__device__ int g_seg[NF + 1];

// ---------------------------------------------------------------------------
// 32x32 tiled transpose fp32 -> fp16
// ---------------------------------------------------------------------------
__global__ void transpose32_h(const float* __restrict__ in, __half* __restrict__ out,
                              int rows, int cols) {
    __shared__ float tile[32][33];
    int c0 = blockIdx.x * 32;
    int r0 = blockIdx.y * 32;
    int x = threadIdx.x, y = threadIdx.y;
#pragma unroll
    for (int k = 0; k < 32; k += 8)
        tile[y + k][x] = in[(size_t)(r0 + y + k) * cols + (c0 + x)];
    __syncthreads();
#pragma unroll
    for (int k = 0; k < 32; k += 8)
        out[(size_t)(c0 + y + k) * rows + (r0 + x)] = __float2half_rn(tile[x][y + k]);
}

// ---------------------------------------------------------------------------
// Segment boundaries: g_seg[f] = first m with i_indices[m] >= f (i sorted).
// ---------------------------------------------------------------------------
__global__ void segstart_kernel(const int* __restrict__ iidx) {
    int f = blockIdx.x * blockDim.x + threadIdx.x;
    if (f > NF) return;
    int lo = 0, hi = NM;
    while (lo < hi) {
        int mid = (lo + hi) >> 1;
        if (iidx[mid] < f) lo = mid + 1; else hi = mid;
    }
    g_seg[f] = lo;
}

// ---------------------------------------------------------------------------
// values v4: warp per VG=8 consecutive connections; fp32 Enc row cached in
// registers across equal sorted i (avg run 16 -> ~1.44 Enc loads per warp,
// vs 1.75 loads over 4 conns before => Enc stream 233MB -> 143MB).
// fp16 Dec rows (403MB L2 stream, the floor).
// ---------------------------------------------------------------------------
#define VG 8
__device__ __forceinline__ float dot8(float4 a_lo, float4 a_hi, float4 hraw, float s) {
    const __half2* h = (const __half2*)&hraw;
    float2 u0 = __half22float2(h[0]);
    float2 u1 = __half22float2(h[1]);
    float2 u2 = __half22float2(h[2]);
    float2 u3 = __half22float2(h[3]);
    s += a_lo.x * u0.x + a_lo.y * u0.y + a_lo.z * u1.x + a_lo.w * u1.y;
    s += a_hi.x * u2.x + a_hi.y * u2.y + a_hi.z * u3.x + a_hi.w * u3.y;
    return s;
}

__global__ void values_kernel(const float* __restrict__ enc,
                              const int* __restrict__ iidx,
                              const int* __restrict__ jidx) {
    int warp = (blockIdx.x * blockDim.x + threadIdx.x) >> 5;
    int lane = threadIdx.x & 31;
    int m0 = warp * VG;
    if (m0 >= NM) return;

    float4 a0, a1, a2, a3, a4, a5;
    int prev_i = -1;

#pragma unroll
    for (int g = 0; g < VG; g++) {
        int m = m0 + g;
        int i = iidx[m];
        int j = jidx[m];
        if (i != prev_i) {
            const float4* ap = (const float4*)(enc + (size_t)i * ND);
            a0 = ap[2 * lane];       a1 = ap[2 * lane + 1];
            a2 = ap[2 * lane + 64];  a3 = ap[2 * lane + 65];
            a4 = ap[2 * lane + 128]; a5 = ap[2 * lane + 129];
            prev_i = i;
        }
        const float4* bp = (const float4*)(g_decH + (size_t)j * ND);
        float4 q0 = bp[lane];
        float4 q1 = bp[lane + 32];
        float4 q2 = bp[lane + 64];

        float s = 0.f;
        s = dot8(a0, a1, q0, s);
        s = dot8(a2, a3, q1, s);
        s = dot8(a4, a5, q2, s);

#pragma unroll
        for (int off = 16; off; off >>= 1)
            s += __shfl_xor_sync(0xFFFFFFFFu, s, off);
        if (lane == 0) g_vals[m] = s;
    }
}

// ---------------------------------------------------------------------------
// Scatter v5: fused segment-reduce + output transpose, single-pass walk.
// CTA = TF=8 features x full 1024 bs, 256 threads (thread t owns columns
// 4t..4t+3 => one 8B load per connection => 2KB full-row wavefront).
// Stage (j, v, local-feature-id) for the CTA's whole range once, then ONE
// loop over all staged connections carrying the accumulator; flush to the
// smem tile at (warp-uniform, rare) feature boundaries. Tile rows padded to
// 1028 floats: 16B-aligned STS.128 flushes AND conflict-free (4c+r) final
// transpose-read. Tile zero-init covers empty features.
// ---------------------------------------------------------------------------
#define TF    8
#define TROW  (NBS + 4)
#define SSTG  512
__global__ void __launch_bounds__(256) scatter_kernel(const int* __restrict__ jidx,
                                                      float* __restrict__ out) {
    __shared__ float tile[TF][TROW];       // 8 x 1028 floats = 32.9 KB
    __shared__ int   sj[SSTG];
    __shared__ float sv[SSTG];
    __shared__ unsigned char si[SSTG];
    __shared__ int   sseg[TF + 1];

    int f0 = blockIdx.x * TF;
    int t  = threadIdx.x;                  // 0..255

    if (t <= TF) sseg[t] = g_seg[f0 + t];
    // zero tile (covers empty features)
    for (int k = t; k < TF * TROW; k += 256) ((float*)tile)[k] = 0.f;
    __syncthreads();

    int mbase = sseg[0];
    int total = sseg[TF] - mbase;
    const float2* up2 = (const float2*)g_upH;   // [F][BS/4] (4 halves each)

    if (total > 0 && total <= SSTG) {
        // ---- stage (j, v, feature) once ----
        for (int k = t; k < total; k += 256) {
            sj[k] = jidx[mbase + k];
            sv[k] = g_vals[mbase + k];
            int gm = mbase + k, lf = 0;
#pragma unroll
            for (int q = 1; q < TF; q++) lf += (gm >= sseg[q]);
            si[k] = (unsigned char)lf;
        }
        __syncthreads();

        float ax = 0.f, ay = 0.f, az = 0.f, aw = 0.f;
        int cur = si[0];
#pragma unroll 4
        for (int k = 0; k < total; k++) {
            int fi = si[k];
            if (fi != cur) {               // warp-uniform, ~8 taken per CTA
                tile[cur][4 * t]     = ax;
                tile[cur][4 * t + 1] = ay;
                tile[cur][4 * t + 2] = az;
                tile[cur][4 * t + 3] = aw;
                ax = ay = az = aw = 0.f;
                cur = fi;
            }
            float  v   = sv[k];
            float2 raw = up2[(size_t)sj[k] * (NBS / 4) + t];
            float2 u0 = __half22float2(*(__half2*)&raw.x);
            float2 u1 = __half22float2(*(__half2*)&raw.y);
            ax += v * u0.x; ay += v * u0.y;
            az += v * u1.x; aw += v * u1.y;
        }
        tile[cur][4 * t]     = ax;
        tile[cur][4 * t + 1] = ay;
        tile[cur][4 * t + 2] = az;
        tile[cur][4 * t + 3] = aw;
    } else if (total > 0) {
        // ---- fallback: per-feature chunking (rare) ----
        for (int lf = 0; lf < TF; lf++) {
            int s0 = sseg[lf], s1 = sseg[lf + 1];
            float ax = 0.f, ay = 0.f, az = 0.f, aw = 0.f;
            for (int base = s0; base < s1; base += SSTG) {
                int len = min(SSTG, s1 - base);
                __syncthreads();
                for (int k = t; k < len; k += 256) {
                    sj[k] = jidx[base + k];
                    sv[k] = g_vals[base + k];
                }
                __syncthreads();
                for (int k = 0; k < len; k++) {
                    float v = sv[k];
                    float2 raw = up2[(size_t)sj[k] * (NBS / 4) + t];
                    float2 u0 = __half22float2(*(__half2*)&raw.x);
                    float2 u1 = __half22float2(*(__half2*)&raw.y);
                    ax += v * u0.x; ay += v * u0.y;
                    az += v * u1.x; aw += v * u1.y;
                }
            }
            tile[lf][4 * t]     = ax;
            tile[lf][4 * t + 1] = ay;
            tile[lf][4 * t + 2] = az;
            tile[lf][4 * t + 3] = aw;
        }
    }
    __syncthreads();

    // Write 8 x 1024 tile to out[r][f0 + c]; tile read tile[c][r]:
    // addr = c*1028 + r -> bank (4c + r) % 32, all 32 distinct per warp.
    for (int idx = t; idx < TF * NBS; idx += 256) {
        int c = idx & (TF - 1);
        int r = idx >> 3;
        out[(size_t)r * NF + f0 + c] = tile[c][r];
    }
}

// ---------------------------------------------------------------------------
extern "C" void kernel_launch(void* const* d_in, const int* in_sizes, int n_in,
                              void* d_out, int out_size) {
    const float* up_facts = (const float*)d_in[0];  // [BS, F]
    const float* enc      = (const float*)d_in[1];  // [F, D]  down_encoder
    const float* dec      = (const float*)d_in[2];  // [D, F]  up_decoder
    const int*   iidx     = (const int*)d_in[3];    // [M] int32, sorted
    const int*   jidx     = (const int*)d_in[4];    // [M] int32
    float*       out      = (float*)d_out;          // [BS, F]

    __half* decH = nullptr; __half* upH = nullptr;
    cudaGetSymbolAddress((void**)&decH, g_decH);
    cudaGetSymbolAddress((void**)&upH,  g_upH);

    dim3 tb(32, 8);

    // 1. Dec [D,F] -> decH [F,D] fp16
    transpose32_h<<<dim3(NF / 32, ND / 32), tb>>>(dec, decH, ND, NF);
    // 2. up_facts [BS,F] -> upH [F,BS] fp16
    transpose32_h<<<dim3(NF / 32, NBS / 32), tb>>>(up_facts, upH, NBS, NF);
    // 3. segment starts
    segstart_kernel<<<(NF + 1 + 255) / 256, 256>>>(iidx);
    // 4. per-connection dot products
    values_kernel<<<(NM / VG) * 32 / 256, 256>>>(enc, iidx, jidx);
    // 5. fused segment reduction + transpose into out
    scatter_kernel<<<NF / TF, 256>>>(jidx, out);
}

// round 9
// speedup vs baseline: 1.3271x; 1.3271x over previous
#include <cuda_runtime.h>
#include <cuda_fp16.h>
#include <cstdint>

#define NF  16384   // n_features
#define ND  768     // d_model
#define NBS 1024    // B*S
#define NM  262144  // n_connections

// Scratch (device globals — no cudaMalloc allowed)
__device__ __align__(16) __half g_decH[(size_t)NF * ND];   // up_decoder transposed [F, D] fp16
__device__ __align__(16) __half g_upH [(size_t)NF * NBS];  // up_facts transposed  [F, BS] fp16
__device__ __align__(16) float  g_vals[NM];
__device__ int g_seg[NF + 1];

// ---------------------------------------------------------------------------
// 32x32 tiled transpose fp32 -> fp16
// ---------------------------------------------------------------------------
__global__ void transpose32_h(const float* __restrict__ in, __half* __restrict__ out,
                              int rows, int cols) {
    __shared__ float tile[32][33];
    int c0 = blockIdx.x * 32;
    int r0 = blockIdx.y * 32;
    int x = threadIdx.x, y = threadIdx.y;
#pragma unroll
    for (int k = 0; k < 32; k += 8)
        tile[y + k][x] = in[(size_t)(r0 + y + k) * cols + (c0 + x)];
    __syncthreads();
#pragma unroll
    for (int k = 0; k < 32; k += 8)
        out[(size_t)(c0 + y + k) * rows + (r0 + x)] = __float2half_rn(tile[x][y + k]);
}

// ---------------------------------------------------------------------------
// Segment boundaries: g_seg[f] = first m with i_indices[m] >= f (i sorted).
// ---------------------------------------------------------------------------
__global__ void segstart_kernel(const int* __restrict__ iidx) {
    int f = blockIdx.x * blockDim.x + threadIdx.x;
    if (f > NF) return;
    int lo = 0, hi = NM;
    while (lo < hi) {
        int mid = (lo + hi) >> 1;
        if (iidx[mid] < f) lo = mid + 1; else hi = mid;
    }
    g_seg[f] = lo;
}

// ---------------------------------------------------------------------------
// values v4 (measured 42.9us): warp per VG=8 consecutive connections; fp32
// Enc row cached in registers across equal sorted i; fp16 Dec rows.
// ---------------------------------------------------------------------------
#define VG 8
__device__ __forceinline__ float dot8(float4 a_lo, float4 a_hi, float4 hraw, float s) {
    const __half2* h = (const __half2*)&hraw;
    float2 u0 = __half22float2(h[0]);
    float2 u1 = __half22float2(h[1]);
    float2 u2 = __half22float2(h[2]);
    float2 u3 = __half22float2(h[3]);
    s += a_lo.x * u0.x + a_lo.y * u0.y + a_lo.z * u1.x + a_lo.w * u1.y;
    s += a_hi.x * u2.x + a_hi.y * u2.y + a_hi.z * u3.x + a_hi.w * u3.y;
    return s;
}

__global__ void values_kernel(const float* __restrict__ enc,
                              const int* __restrict__ iidx,
                              const int* __restrict__ jidx) {
    int warp = (blockIdx.x * blockDim.x + threadIdx.x) >> 5;
    int lane = threadIdx.x & 31;
    int m0 = warp * VG;
    if (m0 >= NM) return;

    float4 a0, a1, a2, a3, a4, a5;
    int prev_i = -1;

#pragma unroll
    for (int g = 0; g < VG; g++) {
        int m = m0 + g;
        int i = iidx[m];
        int j = jidx[m];
        if (i != prev_i) {
            const float4* ap = (const float4*)(enc + (size_t)i * ND);
            a0 = ap[2 * lane];       a1 = ap[2 * lane + 1];
            a2 = ap[2 * lane + 64];  a3 = ap[2 * lane + 65];
            a4 = ap[2 * lane + 128]; a5 = ap[2 * lane + 129];
            prev_i = i;
        }
        const float4* bp = (const float4*)(g_decH + (size_t)j * ND);
        float4 q0 = bp[lane];
        float4 q1 = bp[lane + 32];
        float4 q2 = bp[lane + 64];

        float s = 0.f;
        s = dot8(a0, a1, q0, s);
        s = dot8(a2, a3, q1, s);
        s = dot8(a4, a5, q2, s);

#pragma unroll
        for (int off = 16; off; off >>= 1)
            s += __shfl_xor_sync(0xFFFFFFFFu, s, off);
        if (lane == 0) g_vals[m] = s;
    }
}

// ---------------------------------------------------------------------------
// Scatter v6: fused segment-reduce + output transpose.
// CTA = TF=8 features x full 1024 bs. 256 threads = 2 groups x 128:
//   group g handles features 4g..4g+3; thread u (0..127) owns columns
//   8u..8u+7 -> one float4 (8 halves, 16B) per connection; 128 x 16B = 2KB
//   full-row wavefront. Branch-free inner loops (the R8 lesson), unroll 4.
// Two independent segment walks per CTA => 2x loads in flight, half the
// load-issue count vs 8B loads. Output staged in padded smem tile, written
// directly in out[bs,f] layout.
// ---------------------------------------------------------------------------
#define TF    8
#define TROW  (NBS + 4)
#define SSTG  512

__device__ __forceinline__ void fma8(float* a, float v, float4 raw) {
    const __half2* h = (const __half2*)&raw;
    float2 u0 = __half22float2(h[0]);
    float2 u1 = __half22float2(h[1]);
    float2 u2 = __half22float2(h[2]);
    float2 u3 = __half22float2(h[3]);
    a[0] += v * u0.x; a[1] += v * u0.y;
    a[2] += v * u1.x; a[3] += v * u1.y;
    a[4] += v * u2.x; a[5] += v * u2.y;
    a[6] += v * u3.x; a[7] += v * u3.y;
}

__global__ void __launch_bounds__(256) scatter_kernel(const int* __restrict__ jidx,
                                                      float* __restrict__ out) {
    __shared__ float tile[TF][TROW];       // 8 x 1028 floats
    __shared__ int   sj[SSTG];
    __shared__ float sv[SSTG];
    __shared__ int   sseg[TF + 1];

    int f0 = blockIdx.x * TF;
    int t  = threadIdx.x;                  // 0..255
    int g  = t >> 7;                       // feature group 0/1
    int u  = t & 127;                      // lane in group

    if (t <= TF) sseg[t] = g_seg[f0 + t];
    for (int k = t; k < TF * TROW; k += 256) ((float*)tile)[k] = 0.f;
    __syncthreads();

    int mbase = sseg[0];
    int total = sseg[TF] - mbase;
    const float4* up4 = (const float4*)g_upH;   // [F][128] x 16B

    if (total <= SSTG) {
        // ---- fast path: stage (j, v) once ----
        for (int k = t; k < total; k += 256) {
            sj[k] = jidx[mbase + k];
            sv[k] = g_vals[mbase + k];
        }
        __syncthreads();
#pragma unroll
        for (int lf = 4 * g; lf < 4 * g + 4; lf++) {
            int s0 = sseg[lf] - mbase, s1 = sseg[lf + 1] - mbase;
            float acc[8] = {0.f, 0.f, 0.f, 0.f, 0.f, 0.f, 0.f, 0.f};
#pragma unroll 4
            for (int k = s0; k < s1; k++) {
                float  v   = sv[k];
                float4 raw = up4[(size_t)sj[k] * (NBS / 8) + u];
                fma8(acc, v, raw);
            }
            float4* dst = (float4*)&tile[lf][8 * u];
            dst[0] = make_float4(acc[0], acc[1], acc[2], acc[3]);
            dst[1] = make_float4(acc[4], acc[5], acc[6], acc[7]);
        }
    } else {
        // ---- fallback: chunk-outer / feature-inner (CTA-uniform syncs) ----
        int mend = sseg[TF];
        for (int base = mbase; base < mend; base += SSTG) {
            int len = min(SSTG, mend - base);
            __syncthreads();
            for (int k = t; k < len; k += 256) {
                sj[k] = jidx[base + k];
                sv[k] = g_vals[base + k];
            }
            __syncthreads();
#pragma unroll
            for (int lf = 4 * g; lf < 4 * g + 4; lf++) {
                int s0 = max(sseg[lf], base) - base;
                int s1 = min(sseg[lf + 1], base + len) - base;
                float acc[8] = {0.f, 0.f, 0.f, 0.f, 0.f, 0.f, 0.f, 0.f};
                for (int k = s0; k < s1; k++) {
                    float  v   = sv[k];
                    float4 raw = up4[(size_t)sj[k] * (NBS / 8) + u];
                    fma8(acc, v, raw);
                }
#pragma unroll
                for (int c = 0; c < 8; c++) tile[lf][8 * u + c] += acc[c];
            }
        }
    }
    __syncthreads();

    // Write 8 x 1024 tile to out[r][f0 + c]; tile read tile[c][r]:
    // addr = c*1028 + r -> bank (4c + r) % 32, all 32 distinct per warp.
    for (int idx = t; idx < TF * NBS; idx += 256) {
        int c = idx & (TF - 1);
        int r = idx >> 3;
        out[(size_t)r * NF + f0 + c] = tile[c][r];
    }
}

// ---------------------------------------------------------------------------
extern "C" void kernel_launch(void* const* d_in, const int* in_sizes, int n_in,
                              void* d_out, int out_size) {
    const float* up_facts = (const float*)d_in[0];  // [BS, F]
    const float* enc      = (const float*)d_in[1];  // [F, D]  down_encoder
    const float* dec      = (const float*)d_in[2];  // [D, F]  up_decoder
    const int*   iidx     = (const int*)d_in[3];    // [M] int32, sorted
    const int*   jidx     = (const int*)d_in[4];    // [M] int32
    float*       out      = (float*)d_out;          // [BS, F]

    __half* decH = nullptr; __half* upH = nullptr;
    cudaGetSymbolAddress((void**)&decH, g_decH);
    cudaGetSymbolAddress((void**)&upH,  g_upH);

    dim3 tb(32, 8);

    // 1. Dec [D,F] -> decH [F,D] fp16
    transpose32_h<<<dim3(NF / 32, ND / 32), tb>>>(dec, decH, ND, NF);
    // 2. up_facts [BS,F] -> upH [F,BS] fp16
    transpose32_h<<<dim3(NF / 32, NBS / 32), tb>>>(up_facts, upH, NBS, NF);
    // 3. segment starts
    segstart_kernel<<<(NF + 1 + 255) / 256, 256>>>(iidx);
    // 4. per-connection dot products
    values_kernel<<<(NM / VG) * 32 / 256, 256>>>(enc, iidx, jidx);
    // 5. fused segment reduction + transpose into out
    scatter_kernel<<<NF / TF, 256>>>(jidx, out);
}